// round 9
// baseline (speedup 1.0000x reference)
#include <cuda_runtime.h>
#include <cuda_fp16.h>
#include <mma.h>
#include <stdint.h>

using namespace nvcuda;

// Problem dims
#define BATCH   256
#define TSEQ    1024
#define IN_D    128
#define HID     256
#define OUT_D   128

// Partitioning: 16 batch-groups x 8 unit-group CTAs (cluster of 8 per batch group)
#define NBG     16
#define NUG     8
#define MB      16            // batch rows per group
#define UPC     32            // hidden units per CTA
#define NROWS   128           // gate rows per CTA
#define KDIM    384           // [h(256) | x(128)]
#define KPAD    392           // padded K stride (halves)
#define ZPAD    132           // padded z stride (floats)
#define NTH     256
#define KH      16            // h-part k-steps
#define KSTEPS  24

#define SW_ELEMS (NROWS*KPAD)          // 50176 halves
#define SA_ELEMS (MB*KPAD)             // 6272 halves per buffer

// smem byte offsets
#define OFF_FLAG 0                                  // u32 flags[2][8] = 64 B
#define OFF_SW   64
#define OFF_SA   (OFF_SW + SW_ELEMS*2)              // 100416
#define OFF_SZ   (OFF_SA + 2*SA_ELEMS*2)            // 125504
#define OFF_SB   (OFF_SZ + MB*ZPAD*4)               // 133952
#define OFF_SH   (OFF_SB + NROWS*4)                 // 134464
#define SMEM_BYTES (OFF_SH + MB*UPC*2)              // 135488

__device__ float g_h32[BATCH*HID];   // fp32 h_T for final projection

__device__ __forceinline__ float tanh_fast(float x) {
    float e = __expf(2.0f * x);
    return 1.0f - 2.0f / (e + 1.0f);
}
__device__ __forceinline__ float sigm_fast(float x) {
    return 1.0f / (1.0f + __expf(-x));
}
__device__ __forceinline__ uint32_t elect1() {
    uint32_t p;
    asm volatile("{\n\t.reg .pred p;\n\telect.sync _|p, 0xFFFFFFFF;\n\tselp.b32 %0,1,0,p;\n\t}"
                 : "=r"(p));
    return p;
}
__device__ __forceinline__ void remote_st_v4(uint32_t dst_local, uint32_t rank, uint4 v) {
    asm volatile(
        "{\n\t.reg .b32 ra;\n\t"
        "mapa.shared::cluster.u32 ra, %0, %1;\n\t"
        "st.shared::cluster.v4.u32 [ra], {%2,%3,%4,%5};\n\t}"
        :: "r"(dst_local), "r"(rank), "r"(v.x), "r"(v.y), "r"(v.z), "r"(v.w)
        : "memory");
}
__device__ __forceinline__ void remote_flag_st(uint32_t flag_local, uint32_t rank, uint32_t val) {
    asm volatile(
        "{\n\t.reg .b32 ra;\n\t"
        "mapa.shared::cluster.u32 ra, %0, %1;\n\t"
        "st.relaxed.cluster.shared::cluster.u32 [ra], %2;\n\t}"
        :: "r"(flag_local), "r"(rank), "r"(val)
        : "memory");
}

__global__ void __launch_bounds__(NTH, 1) __cluster_dims__(NUG, 1, 1)
lstm_flag_kernel(const float* __restrict__ x,
                 const float* __restrict__ Wgx, const float* __restrict__ bgx, const float* __restrict__ Wgh,
                 const float* __restrict__ Wix, const float* __restrict__ bix, const float* __restrict__ Wih,
                 const float* __restrict__ Wfx, const float* __restrict__ bfx, const float* __restrict__ Wfh,
                 const float* __restrict__ Wox, const float* __restrict__ boxp, const float* __restrict__ Woh,
                 const float* __restrict__ Wp, const float* __restrict__ bp,
                 float* __restrict__ out)
{
    extern __shared__ unsigned char smem_raw[];
    const uint32_t smb = (uint32_t)__cvta_generic_to_shared(smem_raw);
    uint32_t* sFlag = (uint32_t*)(smem_raw + OFF_FLAG);
    __half* sW    = (__half*)(smem_raw + OFF_SW);
    __half* sA    = (__half*)(smem_raw + OFF_SA);     // [2][MB][KPAD]
    float*  sZ    = (float*)(smem_raw + OFF_SZ);
    float*  sBias = (float*)(smem_raw + OFF_SB);
    __half* sH    = (__half*)(smem_raw + OFF_SH);     // [MB][UPC]

    const int tid  = threadIdx.x;
    const int warp = tid >> 5;
    const int lid  = tid & 31;
    const int ug   = blockIdx.x % NUG;     // cluster rank
    const int bg   = blockIdx.x / NUG;

    // ---- flags init ----
    if (tid < 16) sFlag[tid] = 0u;

    // ---- Load weight slice into smem fp16: row n = gate*32+u, cols [Wh(256)|Wx(128)] ----
    {
        const float* WhA[4] = {Wgh, Wih, Wfh, Woh};
        const float* WxA[4] = {Wgx, Wix, Wfx, Wox};
        #pragma unroll
        for (int g = 0; g < 4; ++g) {
            const float* wh = WhA[g];
            const float* wx = WxA[g];
            for (int idx = tid; idx < UPC*KDIM; idx += NTH) {
                int ul = idx / KDIM;
                int k  = idx - ul*KDIM;
                int n  = g*UPC + ul;
                int ugl = ug*UPC + ul;
                float w = (k < HID) ? wh[ugl*HID + k] : wx[ugl*IN_D + (k - HID)];
                sW[n*KPAD + k] = __float2half_rn(w);
            }
        }
        if (tid < UPC) {
            const float* bxA[4] = {bgx, bix, bfx, boxp};
            #pragma unroll
            for (int g = 0; g < 4; ++g)
                sBias[g*UPC + tid] = bxA[g][ug*UPC + tid];
        }
    }

    // ---- Init: zero h region of buf0; x_0 -> buf0.x, x_1 -> buf1.x ----
    {
        for (int i = tid; i < MB*HID/2; i += NTH) {
            int row = i >> 7;
            int w2  = i & 127;
            *(uint32_t*)&sA[row*KPAD + w2*2] = 0u;
        }
        int row = tid >> 4;
        int q   = (tid & 15) * 8;
        #pragma unroll
        for (int bu = 0; bu < 2; ++bu) {
            const float* src = &x[(bg*MB + row)*(TSEQ*IN_D) + bu*IN_D + q];
            float4 v0 = *(const float4*)src;
            float4 v1 = *(const float4*)(src + 4);
            __half2 h0 = __floats2half2_rn(v0.x, v0.y), h1 = __floats2half2_rn(v0.z, v0.w);
            __half2 h2 = __floats2half2_rn(v1.x, v1.y), h3 = __floats2half2_rn(v1.z, v1.w);
            uint4 pk; pk.x = *(uint32_t*)&h0; pk.y = *(uint32_t*)&h1;
            pk.z = *(uint32_t*)&h2; pk.w = *(uint32_t*)&h3;
            *(uint4*)&sA[bu*SA_ELEMS + row*KPAD + HID + q] = pk;
        }
    }
    __syncthreads();

    // cluster-wide: flags/smem init done everywhere before any DSMEM traffic
    asm volatile("barrier.cluster.arrive.aligned;" ::: "memory");
    asm volatile("barrier.cluster.wait.aligned;"   ::: "memory");

    // ---- B fragments in registers (loop-invariant weights) ----
    wmma::fragment<wmma::matrix_a, 16,16,16, __half, wmma::row_major> fa;
    wmma::fragment<wmma::matrix_b, 16,16,16, __half, wmma::col_major> fbr[KSTEPS];
    wmma::fragment<wmma::accumulator, 16,16,16, float> fc, fc2;
    const int n0 = warp * 16;
    #pragma unroll
    for (int kk = 0; kk < KSTEPS; ++kk)
        wmma::load_matrix_sync(fbr[kk], sW + n0*KPAD + kk*16, KPAD);

    // ---- Pre-loop X phase: fc = x_0 @ Wx^T (from buf0.x) ----
    wmma::fill_fragment(fc, 0.0f);
    #pragma unroll
    for (int kk = KH; kk < KSTEPS; ++kk) {
        wmma::load_matrix_sync(fa, sA + kk*16, KPAD);
        wmma::mma_sync(fc, fa, fbr[kk], fc);
    }

    // epilogue mapping
    const int b0 = tid >> 5;
    const int uu = tid & 31;
    float c0 = 0.0f, c1 = 0.0f;

    for (int t = 0; t < TSEQ; ++t) {
        const int p = t & 1;

        // ---- prefetch x_{t+2} into regs (off critical path) ----
        float4 xv0, xv1;
        {
            int tn  = (t + 2 < TSEQ) ? (t + 2) : (TSEQ - 1);
            int row = tid >> 4;
            int q   = (tid & 15) * 8;
            const float* src = &x[(bg*MB + row)*(TSEQ*IN_D) + tn*IN_D + q];
            xv0 = *(const float4*)src;
            xv1 = *(const float4*)(src + 4);
        }

        // ---- wait for h tile (buffer p): local smem flag spin ----
        if (t > 0) {
            uint32_t faddr = smb + OFF_FLAG + (uint32_t)((p*8 + (lid & 7))*4);
            uint32_t v;
            do {
                asm volatile("ld.relaxed.cluster.shared::cta.u32 %0, [%1];"
                             : "=r"(v) : "r"(faddr));
            } while ((int)v < t);
            asm volatile("fence.acq_rel.cluster;" ::: "memory");
        }

        // ---- Phase H: accumulate h-part (k = 0..255), dual accumulator ----
        const __half* sAp = sA + p*SA_ELEMS;
        wmma::fill_fragment(fc2, 0.0f);
        #pragma unroll
        for (int kk = 0; kk < KH; kk += 2) {
            wmma::load_matrix_sync(fa, sAp + kk*16, KPAD);
            wmma::mma_sync(fc, fa, fbr[kk], fc);
            wmma::load_matrix_sync(fa, sAp + (kk+1)*16, KPAD);
            wmma::mma_sync(fc2, fa, fbr[kk+1], fc2);
        }
        #pragma unroll
        for (int e = 0; e < fc.num_elements; ++e) fc.x[e] += fc2.x[e];
        wmma::store_matrix_sync(sZ + n0, fc, ZPAD, wmma::mem_row_major);
        __syncthreads();

        // ---- Epilogue: gates, c/h update -> sH ----
        #pragma unroll
        for (int j = 0; j < 2; ++j) {
            int b = b0 + j*8;
            const float* zr = &sZ[b*ZPAD];
            float zg = zr[uu]          + sBias[uu];
            float zi = zr[UPC   + uu]  + sBias[UPC   + uu];
            float zf = zr[2*UPC + uu]  + sBias[2*UPC + uu];
            float zo = zr[3*UPC + uu]  + sBias[3*UPC + uu];
            float gv = tanh_fast(zg);
            float iv = sigm_fast(zi);
            float fv = sigm_fast(zf);
            float ov = sigm_fast(zo);
            float& c = j ? c1 : c0;
            c = gv*iv + c*fv;
            float h = tanh_fast(c) * ov;
            sH[b*UPC + uu] = __float2half_rn(h);
            if (t == TSEQ-1) g_h32[(bg*MB + b)*HID + ug*UPC + uu] = h;
        }
        __syncthreads();

        // ---- Push own h slice (1 KB) to rank==warp's buffer p^1, then set its flag ----
        if (t < TSEQ-1) {
            const int q = p ^ 1;
            #pragma unroll
            for (int j = 0; j < 2; ++j) {
                int c    = lid + j*32;        // 16B chunk 0..63
                int row  = c >> 2;
                int q4   = c & 3;
                uint4 v = *(const uint4*)((const unsigned char*)sH + row*64 + q4*16);
                uint32_t dst_local = smb + OFF_SA +
                    (uint32_t)((q*SA_ELEMS + row*KPAD + ug*UPC + q4*8) * 2);
                remote_st_v4(dst_local, (uint32_t)warp, v);
            }
            asm volatile("fence.acq_rel.cluster;" ::: "memory");
            __syncwarp();
            if (elect1()) {
                uint32_t flag_local = smb + OFF_FLAG + (uint32_t)((q*8 + ug)*4);
                remote_flag_st(flag_local, (uint32_t)warp, (uint32_t)(t + 1));
            }
        }

        // ---- Phase X for step t+1: fc = x_{t+1} @ Wx^T (buffer p^1) — overlaps push ----
        wmma::fill_fragment(fc, 0.0f);
        const __half* sAx = sA + (p^1)*SA_ELEMS;
        #pragma unroll
        for (int kk = KH; kk < KSTEPS; ++kk) {
            wmma::load_matrix_sync(fa, sAx + kk*16, KPAD);
            wmma::mma_sync(fc, fa, fbr[kk], fc);
        }

        // ---- stage x_{t+2} into buffer p x-region ----
        {
            int row = tid >> 4;
            int q   = (tid & 15) * 8;
            __half2 h0 = __floats2half2_rn(xv0.x, xv0.y), h1 = __floats2half2_rn(xv0.z, xv0.w);
            __half2 h2 = __floats2half2_rn(xv1.x, xv1.y), h3 = __floats2half2_rn(xv1.z, xv1.w);
            uint4 pk; pk.x = *(uint32_t*)&h0; pk.y = *(uint32_t*)&h1;
            pk.z = *(uint32_t*)&h2; pk.w = *(uint32_t*)&h3;
            *(uint4*)&sA[p*SA_ELEMS + row*KPAD + HID + q] = pk;
        }
    }

    // ---- make g_h32 visible; keep cluster alive until all traffic done ----
    __threadfence();
    asm volatile("barrier.cluster.arrive.aligned;" ::: "memory");
    asm volatile("barrier.cluster.wait.aligned;"   ::: "memory");

    // ---- Final projection: out = h_T @ Wp^T + bp (fp32), rank-0 CTAs ----
    if (ug == 0) {
        const int b     = tid >> 4;
        const int obase = (tid & 15) * 8;
        float acc[8];
        #pragma unroll
        for (int rr = 0; rr < 8; ++rr) acc[rr] = bp[obase + rr];
        const float* hrow = &g_h32[(bg*MB + b)*HID];
        for (int k = 0; k < HID; ++k) {
            float hv = hrow[k];
            #pragma unroll
            for (int rr = 0; rr < 8; ++rr)
                acc[rr] = fmaf(hv, Wp[(obase + rr)*HID + k], acc[rr]);
        }
        #pragma unroll
        for (int rr = 0; rr < 8; ++rr)
            out[(bg*MB + b)*OUT_D + obase + rr] = acc[rr];
    }
}

extern "C" void kernel_launch(void* const* d_in, const int* in_sizes, int n_in,
                              void* d_out, int out_size) {
    const float* x   = (const float*)d_in[0];
    const float* Wgx = (const float*)d_in[1];
    const float* bgx = (const float*)d_in[2];
    const float* Wgh = (const float*)d_in[3];
    const float* Wix = (const float*)d_in[4];
    const float* bix = (const float*)d_in[5];
    const float* Wih = (const float*)d_in[6];
    const float* Wfx = (const float*)d_in[7];
    const float* bfx = (const float*)d_in[8];
    const float* Wfh = (const float*)d_in[9];
    const float* Wox = (const float*)d_in[10];
    const float* box = (const float*)d_in[11];
    const float* Woh = (const float*)d_in[12];
    const float* Wp  = (const float*)d_in[13];
    const float* bp  = (const float*)d_in[14];
    float* out = (float*)d_out;

    static bool attr_set = false;
    if (!attr_set) {
        cudaFuncSetAttribute(lstm_flag_kernel,
                             cudaFuncAttributeMaxDynamicSharedMemorySize, SMEM_BYTES);
        attr_set = true;
    }

    lstm_flag_kernel<<<NBG*NUG, NTH, SMEM_BYTES>>>(
        x, Wgx, bgx, Wgh, Wix, bix, Wih, Wfx, bfx, Wfh, Wox, box, Woh, Wp, bp, out);
}

// round 10
// speedup vs baseline: 1.3468x; 1.3468x over previous
#include <cuda_runtime.h>
#include <cuda_fp16.h>
#include <mma.h>
#include <stdint.h>

using namespace nvcuda;

// Problem dims
#define BATCH   256
#define TSEQ    1024
#define IN_D    128
#define HID     256
#define OUT_D   128

// Partitioning: 16 batch-groups x 8 unit-group CTAs, global-L2 exchange (NO clusters)
#define NBG     16
#define NUG     8
#define MB      16            // batch rows per group
#define UPC     32            // hidden units per CTA
#define NROWS   128           // gate rows per CTA
#define KDIM    384           // [h(256) | x(128)]
#define KPAD    392           // padded K stride (halves)
#define ZPAD    132           // padded z stride (floats)
#define NTH     256
#define KH      16            // h-part k-steps
#define KSTEPS  24

#define SW_ELEMS (NROWS*KPAD)          // 50176 halves
#define SA_ELEMS (MB*KPAD)             // 6272 halves per buffer

// smem byte offsets
#define OFF_SW   0
#define OFF_SA   (OFF_SW + SW_ELEMS*2)              // 100352
#define OFF_SZ   (OFF_SA + 2*SA_ELEMS*2)            // 125440
#define OFF_SB   (OFF_SZ + MB*ZPAD*4)               // 133888
#define OFF_SH   (OFF_SB + NROWS*4)                 // 134400
#define SMEM_BYTES (OFF_SH + MB*UPC*2)              // 135424

// Device-global state
__device__ __half   g_h[2][BATCH*HID];     // double-buffered hidden state (fp16)
__device__ float    g_h32[BATCH*HID];      // fp32 h_T for final projection
__device__ unsigned g_flag[2][NBG][NUG];   // per-producer publish flags (monotonic)

__device__ __forceinline__ float tanh_fast(float x) {
    float e = __expf(2.0f * x);
    return 1.0f - 2.0f / (e + 1.0f);
}
__device__ __forceinline__ float sigm_fast(float x) {
    return 1.0f / (1.0f + __expf(-x));
}
__device__ __forceinline__ unsigned ld_acquire_gpu(const unsigned* p) {
    unsigned v;
    asm volatile("ld.acquire.gpu.global.u32 %0, [%1];" : "=r"(v) : "l"(p) : "memory");
    return v;
}
__device__ __forceinline__ void st_release_gpu(unsigned* p, unsigned v) {
    asm volatile("st.release.gpu.global.u32 [%0], %1;" :: "l"(p), "r"(v) : "memory");
}

__global__ void lstm_init_kernel() {
    int i = blockIdx.x * blockDim.x + threadIdx.x;
    if (i < 2*NBG*NUG) ((unsigned*)g_flag)[i] = 0u;
}

__global__ void __launch_bounds__(NTH, 1)
lstm_main_kernel(const float* __restrict__ x,
                 const float* __restrict__ Wgx, const float* __restrict__ bgx, const float* __restrict__ Wgh,
                 const float* __restrict__ Wix, const float* __restrict__ bix, const float* __restrict__ Wih,
                 const float* __restrict__ Wfx, const float* __restrict__ bfx, const float* __restrict__ Wfh,
                 const float* __restrict__ Wox, const float* __restrict__ boxp, const float* __restrict__ Woh,
                 const float* __restrict__ Wp, const float* __restrict__ bp,
                 float* __restrict__ out)
{
    extern __shared__ unsigned char smem_raw[];
    __half* sW    = (__half*)(smem_raw + OFF_SW);
    __half* sA    = (__half*)(smem_raw + OFF_SA);     // [2][MB][KPAD]
    float*  sZ    = (float*)(smem_raw + OFF_SZ);
    float*  sBias = (float*)(smem_raw + OFF_SB);
    __half* sH    = (__half*)(smem_raw + OFF_SH);     // [MB][UPC]

    const int tid  = threadIdx.x;
    const int warp = tid >> 5;
    const int lid  = tid & 31;
    const int ug   = blockIdx.x % NUG;
    const int bg   = blockIdx.x / NUG;

    // ---- Load weight slice into smem fp16: row n = gate*32+u, cols [Wh(256)|Wx(128)] ----
    {
        const float* WhA[4] = {Wgh, Wih, Wfh, Woh};
        const float* WxA[4] = {Wgx, Wix, Wfx, Wox};
        #pragma unroll
        for (int g = 0; g < 4; ++g) {
            const float* wh = WhA[g];
            const float* wx = WxA[g];
            for (int idx = tid; idx < UPC*KDIM; idx += NTH) {
                int ul = idx / KDIM;
                int k  = idx - ul*KDIM;
                int n  = g*UPC + ul;
                int ugl = ug*UPC + ul;
                float w = (k < HID) ? wh[ugl*HID + k] : wx[ugl*IN_D + (k - HID)];
                sW[n*KPAD + k] = __float2half_rn(w);
            }
        }
        if (tid < UPC) {
            const float* bxA[4] = {bgx, bix, bfx, boxp};
            #pragma unroll
            for (int g = 0; g < 4; ++g)
                sBias[g*UPC + tid] = bxA[g][ug*UPC + tid];
        }
    }

    // ---- Init: zero h region of buf0; x_0 -> buf0.x, x_1 -> buf1.x ----
    {
        for (int i = tid; i < MB*HID/2; i += NTH) {
            int row = i >> 7;
            int w2  = i & 127;
            *(uint32_t*)&sA[row*KPAD + w2*2] = 0u;
        }
        int row = tid >> 4;
        int q   = (tid & 15) * 8;
        #pragma unroll
        for (int bu = 0; bu < 2; ++bu) {
            const float* src = &x[(bg*MB + row)*(TSEQ*IN_D) + bu*IN_D + q];
            float4 v0 = *(const float4*)src;
            float4 v1 = *(const float4*)(src + 4);
            __half2 h0 = __floats2half2_rn(v0.x, v0.y), h1 = __floats2half2_rn(v0.z, v0.w);
            __half2 h2 = __floats2half2_rn(v1.x, v1.y), h3 = __floats2half2_rn(v1.z, v1.w);
            uint4 pk; pk.x = *(uint32_t*)&h0; pk.y = *(uint32_t*)&h1;
            pk.z = *(uint32_t*)&h2; pk.w = *(uint32_t*)&h3;
            *(uint4*)&sA[bu*SA_ELEMS + row*KPAD + HID + q] = pk;
        }
    }
    __syncthreads();

    // ---- B fragments in registers (loop-invariant weights) ----
    wmma::fragment<wmma::matrix_a, 16,16,16, __half, wmma::row_major> fa;
    wmma::fragment<wmma::matrix_b, 16,16,16, __half, wmma::col_major> fbr[KSTEPS];
    wmma::fragment<wmma::accumulator, 16,16,16, float> fc, fc2;
    const int n0 = warp * 16;
    #pragma unroll
    for (int kk = 0; kk < KSTEPS; ++kk)
        wmma::load_matrix_sync(fbr[kk], sW + n0*KPAD + kk*16, KPAD);

    // ---- Pre-loop X phase: fc = x_0 @ Wx^T (from buf0.x) ----
    wmma::fill_fragment(fc, 0.0f);
    #pragma unroll
    for (int kk = KH; kk < KSTEPS; ++kk) {
        wmma::load_matrix_sync(fa, sA + kk*16, KPAD);
        wmma::mma_sync(fc, fa, fbr[kk], fc);
    }

    // epilogue mapping
    const int b0 = tid >> 5;
    const int uu = tid & 31;
    float c0 = 0.0f, c1 = 0.0f;

    for (int t = 0; t < TSEQ; ++t) {
        const int p = t & 1;

        // ---- prefetch x_{t+2} into regs ----
        float4 xv0, xv1;
        {
            int tn  = (t + 2 < TSEQ) ? (t + 2) : (TSEQ - 1);
            int row = tid >> 4;
            int q   = (tid & 15) * 8;
            const float* src = &x[(bg*MB + row)*(TSEQ*IN_D) + tn*IN_D + q];
            xv0 = *(const float4*)src;
            xv1 = *(const float4*)(src + 4);
        }

        // ---- acquire h_t tile: warp w handles producer w ----
        if (t > 0) {
            const int row = lid >> 1;          // 0..15
            const int seg = lid & 1;           // 32B half-chunk
            __half* dst = &sA[p*SA_ELEMS + row*KPAD + warp*UPC + seg*16];
            if (warp == ug) {
                // own slice from local sH (written last step's epilogue)
                const uint4* src = (const uint4*)((const unsigned char*)sH + row*(UPC*2) + seg*32);
                uint4 v0s = src[0], v1s = src[1];
                ((uint4*)dst)[0] = v0s;
                ((uint4*)dst)[1] = v1s;
            } else {
                if (lid == 0) {
                    const unsigned* fp_ = &g_flag[p][bg][warp];
                    while ((int)ld_acquire_gpu(fp_) < t) { }
                }
                __syncwarp();
                const uint4* src = (const uint4*)&g_h[p][(bg*MB + row)*HID + warp*UPC + seg*16];
                uint4 v0g = __ldcg(src);
                uint4 v1g = __ldcg(src + 1);
                ((uint4*)dst)[0] = v0g;
                ((uint4*)dst)[1] = v1g;
            }
        }
        __syncthreads();

        // ---- Phase H: accumulate h-part (k = 0..255), dual accumulator ----
        const __half* sAp = sA + p*SA_ELEMS;
        wmma::fill_fragment(fc2, 0.0f);
        #pragma unroll
        for (int kk = 0; kk < KH; kk += 2) {
            wmma::load_matrix_sync(fa, sAp + kk*16, KPAD);
            wmma::mma_sync(fc, fa, fbr[kk], fc);
            wmma::load_matrix_sync(fa, sAp + (kk+1)*16, KPAD);
            wmma::mma_sync(fc2, fa, fbr[kk+1], fc2);
        }
        #pragma unroll
        for (int e = 0; e < fc.num_elements; ++e) fc.x[e] += fc2.x[e];
        wmma::store_matrix_sync(sZ + n0, fc, ZPAD, wmma::mem_row_major);
        __syncthreads();

        // ---- Epilogue: gates, c/h update -> sH (and g_h32 at last step) ----
        #pragma unroll
        for (int j = 0; j < 2; ++j) {
            int b = b0 + j*8;
            const float* zr = &sZ[b*ZPAD];
            float zg = zr[uu]          + sBias[uu];
            float zi = zr[UPC   + uu]  + sBias[UPC   + uu];
            float zf = zr[2*UPC + uu]  + sBias[2*UPC + uu];
            float zo = zr[3*UPC + uu]  + sBias[3*UPC + uu];
            float gv = tanh_fast(zg);
            float iv = sigm_fast(zi);
            float fv = sigm_fast(zf);
            float ov = sigm_fast(zo);
            float& c = j ? c1 : c0;
            c = gv*iv + c*fv;
            float h = tanh_fast(c) * ov;
            sH[b*UPC + uu] = __float2half_rn(h);
            if (t == TSEQ-1) g_h32[(bg*MB + b)*HID + ug*UPC + uu] = h;
        }
        __syncthreads();

        // ---- Publish own 1KB slice (weak STG) + release flag ----
        const int q = p ^ 1;
        if (t < TSEQ-1 && tid < 64) {
            int row = tid >> 2, c4 = tid & 3;
            uint4 v = *(const uint4*)((const unsigned char*)sH + row*(UPC*2) + c4*16);
            *(uint4*)&g_h[q][(bg*MB + row)*HID + ug*UPC + c4*8] = v;
        }
        __syncthreads();
        if (tid == 0)
            st_release_gpu(&g_flag[q][bg][ug], (unsigned)(t + 1));

        // ---- Phase X for step t+1: fc = x_{t+1} @ Wx^T (buffer p^1) — overlaps comm ----
        wmma::fill_fragment(fc, 0.0f);
        const __half* sAx = sA + (p^1)*SA_ELEMS;
        #pragma unroll
        for (int kk = KH; kk < KSTEPS; ++kk) {
            wmma::load_matrix_sync(fa, sAx + kk*16, KPAD);
            wmma::mma_sync(fc, fa, fbr[kk], fc);
        }

        // ---- stage x_{t+2} into buffer p x-region ----
        {
            int row = tid >> 4;
            int qq  = (tid & 15) * 8;
            __half2 h0 = __floats2half2_rn(xv0.x, xv0.y), h1 = __floats2half2_rn(xv0.z, xv0.w);
            __half2 h2 = __floats2half2_rn(xv1.x, xv1.y), h3 = __floats2half2_rn(xv1.z, xv1.w);
            uint4 pk; pk.x = *(uint32_t*)&h0; pk.y = *(uint32_t*)&h1;
            pk.z = *(uint32_t*)&h2; pk.w = *(uint32_t*)&h3;
            *(uint4*)&sA[p*SA_ELEMS + row*KPAD + HID + qq] = pk;
        }
    }

    // ---- Final projection by ug==0 CTAs: wait for all 8 h_T publications ----
    if (ug == 0) {
        if (tid < NUG) {
            const unsigned* fp_ = &g_flag[0][bg][tid];
            while ((int)ld_acquire_gpu(fp_) < TSEQ) { }
        }
        __syncthreads();

        const int b     = tid >> 4;
        const int obase = (tid & 15) * 8;
        float acc[8];
        #pragma unroll
        for (int rr = 0; rr < 8; ++rr) acc[rr] = bp[obase + rr];
        const float* hrow = &g_h32[(bg*MB + b)*HID];
        for (int k = 0; k < HID; k += 4) {
            float4 hv = __ldcg((const float4*)&hrow[k]);
            #pragma unroll
            for (int rr = 0; rr < 8; ++rr) {
                acc[rr] = fmaf(hv.x, Wp[(obase + rr)*HID + k],     acc[rr]);
                acc[rr] = fmaf(hv.y, Wp[(obase + rr)*HID + k + 1], acc[rr]);
                acc[rr] = fmaf(hv.z, Wp[(obase + rr)*HID + k + 2], acc[rr]);
                acc[rr] = fmaf(hv.w, Wp[(obase + rr)*HID + k + 3], acc[rr]);
            }
        }
        #pragma unroll
        for (int rr = 0; rr < 8; ++rr)
            out[(bg*MB + b)*OUT_D + obase + rr] = acc[rr];
    }
}

extern "C" void kernel_launch(void* const* d_in, const int* in_sizes, int n_in,
                              void* d_out, int out_size) {
    const float* x   = (const float*)d_in[0];
    const float* Wgx = (const float*)d_in[1];
    const float* bgx = (const float*)d_in[2];
    const float* Wgh = (const float*)d_in[3];
    const float* Wix = (const float*)d_in[4];
    const float* bix = (const float*)d_in[5];
    const float* Wih = (const float*)d_in[6];
    const float* Wfx = (const float*)d_in[7];
    const float* bfx = (const float*)d_in[8];
    const float* Wfh = (const float*)d_in[9];
    const float* Wox = (const float*)d_in[10];
    const float* box = (const float*)d_in[11];
    const float* Woh = (const float*)d_in[12];
    const float* Wp  = (const float*)d_in[13];
    const float* bp  = (const float*)d_in[14];
    float* out = (float*)d_out;

    static bool attr_set = false;
    if (!attr_set) {
        cudaFuncSetAttribute(lstm_main_kernel,
                             cudaFuncAttributeMaxDynamicSharedMemorySize, SMEM_BYTES);
        attr_set = true;
    }

    lstm_init_kernel<<<1, 256>>>();
    lstm_main_kernel<<<NBG*NUG, NTH, SMEM_BYTES>>>(
        x, Wgx, bgx, Wgh, Wix, bix, Wih, Wfx, bfx, Wfh, Wox, box, Woh, Wp, bp, out);
}

// round 14
// speedup vs baseline: 1.9409x; 1.4412x over previous
#include <cuda_runtime.h>
#include <cuda_fp16.h>
#include <mma.h>
#include <stdint.h>

using namespace nvcuda;

// Problem dims
#define BATCH   256
#define TSEQ    1024
#define IN_D    128
#define HID     256
#define OUT_D   128

// Partitioning: 16 batch-groups x 8 unit-group CTAs, LL global-L2 exchange
#define NBG     16
#define NUG     8
#define MB      16            // batch rows per group
#define UPC     32            // hidden units per CTA
#define NROWS   128           // gate rows per CTA
#define KDIM    384           // [h(256) | x(128)]
#define KPAD    392           // padded K stride (halves)
#define ZPAD    132           // padded z stride (floats)
#define NTH     256
#define KH      16            // h-part k-steps
#define KSTEPS  24
#define NCHUNK  256           // 8B packets per producer slice (16 rows x 16 unit-pairs)

#define SW_ELEMS (NROWS*KPAD)          // 50176 halves
#define SA_ELEMS (MB*KPAD)             // 6272 halves per buffer

// smem byte offsets
#define OFF_SW   0
#define OFF_SA   (OFF_SW + SW_ELEMS*2)              // 100352
#define OFF_SZ   (OFF_SA + 2*SA_ELEMS*2)            // 125440
#define OFF_SB   (OFF_SZ + MB*ZPAD*4)               // 133888
#define OFF_SH   (OFF_SB + NROWS*4)                 // 134400
#define SMEM_BYTES (OFF_SH + MB*UPC*2)              // 135424

// Device-global state
__device__ unsigned long long g_hx[2][NBG][NUG][NCHUNK];  // LL packets: tag<<32 | 2xfp16
__device__ float    g_h32[BATCH*HID];                      // fp32 h_T for final projection
__device__ unsigned g_done[NBG];                           // completion counters

__device__ __forceinline__ float tanh_fast(float x) {
    float e = __expf(2.0f * x);
    return 1.0f - 2.0f / (e + 1.0f);
}
__device__ __forceinline__ float sigm_fast(float x) {
    return 1.0f / (1.0f + __expf(-x));
}
__device__ __forceinline__ unsigned long long ll_poll(const unsigned long long* p) {
    unsigned long long v;
    asm volatile("ld.global.cg.b64 %0, [%1];" : "=l"(v) : "l"(p) : "memory");
    return v;
}
__device__ __forceinline__ void ll_send(unsigned long long* p, unsigned long long v) {
    asm volatile("st.global.cg.b64 [%0], %1;" :: "l"(p), "l"(v) : "memory");
}
__device__ __forceinline__ unsigned ld_acquire_gpu(const unsigned* p) {
    unsigned v;
    asm volatile("ld.acquire.gpu.global.u32 %0, [%1];" : "=r"(v) : "l"(p) : "memory");
    return v;
}

__global__ void lstm_init_kernel() {
    int i = blockIdx.x * blockDim.x + threadIdx.x;
    int n = 2*NBG*NUG*NCHUNK;                 // 8192 u64
    if (i < n) ((unsigned long long*)g_hx)[i] = 0ull;
    if (i < NBG) g_done[i] = 0u;
}

__global__ void __launch_bounds__(NTH, 1)
lstm_ll_kernel(const float* __restrict__ x,
               const float* __restrict__ Wgx, const float* __restrict__ bgx, const float* __restrict__ Wgh,
               const float* __restrict__ Wix, const float* __restrict__ bix, const float* __restrict__ Wih,
               const float* __restrict__ Wfx, const float* __restrict__ bfx, const float* __restrict__ Wfh,
               const float* __restrict__ Wox, const float* __restrict__ boxp, const float* __restrict__ Woh,
               const float* __restrict__ Wp, const float* __restrict__ bp,
               float* __restrict__ out)
{
    extern __shared__ unsigned char smem_raw[];
    __half* sW    = (__half*)(smem_raw + OFF_SW);
    __half* sA    = (__half*)(smem_raw + OFF_SA);     // [2][MB][KPAD]
    float*  sZ    = (float*)(smem_raw + OFF_SZ);
    float*  sBias = (float*)(smem_raw + OFF_SB);
    __half* sH    = (__half*)(smem_raw + OFF_SH);     // [MB][UPC]

    const int tid  = threadIdx.x;
    const int warp = tid >> 5;
    const int lid  = tid & 31;
    const int ug   = blockIdx.x % NUG;
    const int bg   = blockIdx.x / NUG;

    // ---- Load weight slice into smem fp16: row n = gate*32+u, cols [Wh(256)|Wx(128)] ----
    {
        const float* WhA[4] = {Wgh, Wih, Wfh, Woh};
        const float* WxA[4] = {Wgx, Wix, Wfx, Wox};
        #pragma unroll
        for (int g = 0; g < 4; ++g) {
            const float* wh = WhA[g];
            const float* wx = WxA[g];
            for (int idx = tid; idx < UPC*KDIM; idx += NTH) {
                int ul = idx / KDIM;
                int k  = idx - ul*KDIM;
                int n  = g*UPC + ul;
                int ugl = ug*UPC + ul;
                float w = (k < HID) ? wh[ugl*HID + k] : wx[ugl*IN_D + (k - HID)];
                sW[n*KPAD + k] = __float2half_rn(w);
            }
        }
        if (tid < UPC) {
            const float* bxA[4] = {bgx, bix, bfx, boxp};
            #pragma unroll
            for (int g = 0; g < 4; ++g)
                sBias[g*UPC + tid] = bxA[g][ug*UPC + tid];
        }
    }

    // ---- Init: zero h region of buf0; x_0 -> buf0.x, x_1 -> buf1.x ----
    {
        for (int i = tid; i < MB*HID/2; i += NTH) {
            int row = i >> 7;
            int w2  = i & 127;
            *(uint32_t*)&sA[row*KPAD + w2*2] = 0u;
        }
        int row = tid >> 4;
        int q   = (tid & 15) * 8;
        #pragma unroll
        for (int bu = 0; bu < 2; ++bu) {
            const float* src = &x[(bg*MB + row)*(TSEQ*IN_D) + bu*IN_D + q];
            float4 v0 = *(const float4*)src;
            float4 v1 = *(const float4*)(src + 4);
            __half2 h0 = __floats2half2_rn(v0.x, v0.y), h1 = __floats2half2_rn(v0.z, v0.w);
            __half2 h2 = __floats2half2_rn(v1.x, v1.y), h3 = __floats2half2_rn(v1.z, v1.w);
            uint4 pk; pk.x = *(uint32_t*)&h0; pk.y = *(uint32_t*)&h1;
            pk.z = *(uint32_t*)&h2; pk.w = *(uint32_t*)&h3;
            *(uint4*)&sA[bu*SA_ELEMS + row*KPAD + HID + q] = pk;
        }
    }
    __syncthreads();

    // ---- B fragments in registers (loop-invariant weights) ----
    wmma::fragment<wmma::matrix_a, 16,16,16, __half, wmma::row_major> fa;
    wmma::fragment<wmma::matrix_b, 16,16,16, __half, wmma::col_major> fbr[KSTEPS];
    wmma::fragment<wmma::accumulator, 16,16,16, float> fc, fc2;
    const int n0 = warp * 16;
    #pragma unroll
    for (int kk = 0; kk < KSTEPS; ++kk)
        wmma::load_matrix_sync(fbr[kk], sW + n0*KPAD + kk*16, KPAD);

    // ---- Pre-loop X phase: fc = x_0 @ Wx^T (from buf0.x) ----
    wmma::fill_fragment(fc, 0.0f);
    #pragma unroll
    for (int kk = KH; kk < KSTEPS; ++kk) {
        wmma::load_matrix_sync(fa, sA + kk*16, KPAD);
        wmma::mma_sync(fc, fa, fbr[kk], fc);
    }

    // epilogue mapping: thread (b0=warp, uu=lid) handles rows b0 and b0+8, unit uu
    const int b0 = warp;
    const int uu = lid;
    float c0 = 0.0f, c1 = 0.0f;

    for (int t = 0; t < TSEQ; ++t) {
        const int p = t & 1;

        // ---- prefetch x_{t+2} into regs ----
        float4 xv0, xv1;
        {
            int tn  = (t + 2 < TSEQ) ? (t + 2) : (TSEQ - 1);
            int row = tid >> 4;
            int q   = (tid & 15) * 8;
            const float* src = &x[(bg*MB + row)*(TSEQ*IN_D) + tn*IN_D + q];
            xv0 = *(const float4*)src;
            xv1 = *(const float4*)(src + 4);
        }

        // ---- acquire h_t tile: warp w handles producer w (LL packets) ----
        if (t > 0) {
            if (warp == ug) {
                // own slice from local sH
                const int row = lid >> 1;
                const int seg = lid & 1;
                const uint4* src = (const uint4*)((const unsigned char*)sH + row*(UPC*2) + seg*32);
                uint4 v0s = src[0], v1s = src[1];
                __half* dst = &sA[p*SA_ELEMS + row*KPAD + warp*UPC + seg*16];
                ((uint4*)dst)[0] = v0s;
                ((uint4*)dst)[1] = v1s;
            } else {
                const unsigned long long* src = &g_hx[p][bg][warp][lid*8];
                const unsigned want = (unsigned)t;
                unsigned long long v[8];
                #pragma unroll
                for (int i = 0; i < 8; ++i) v[i] = 0ull;   // tag 0 != t (t>=1)
                int miss = 1;
                while (miss) {
                    #pragma unroll
                    for (int i = 0; i < 8; ++i)
                        if ((unsigned)(v[i] >> 32) != want) v[i] = ll_poll(src + i);
                    miss = 0;
                    #pragma unroll
                    for (int i = 0; i < 8; ++i)
                        miss |= ((unsigned)(v[i] >> 32) != want);
                }
                // scatter payloads: chunk c = r*16 + up  ->  sA[p][r][warp*32 + 2*up]
                #pragma unroll
                for (int i = 0; i < 8; ++i) {
                    int c  = lid*8 + i;
                    int r  = c >> 4;
                    int up = c & 15;
                    *(uint32_t*)&sA[p*SA_ELEMS + r*KPAD + warp*UPC + up*2] = (uint32_t)v[i];
                }
            }
        }
        __syncthreads();

        // ---- Phase H: accumulate h-part (k = 0..255), dual accumulator ----
        const __half* sAp = sA + p*SA_ELEMS;
        wmma::fill_fragment(fc2, 0.0f);
        #pragma unroll
        for (int kk = 0; kk < KH; kk += 2) {
            wmma::load_matrix_sync(fa, sAp + kk*16, KPAD);
            wmma::mma_sync(fc, fa, fbr[kk], fc);
            wmma::load_matrix_sync(fa, sAp + (kk+1)*16, KPAD);
            wmma::mma_sync(fc2, fa, fbr[kk+1], fc2);
        }
        #pragma unroll
        for (int e = 0; e < fc.num_elements; ++e) fc.x[e] += fc2.x[e];
        wmma::store_matrix_sync(sZ + n0, fc, ZPAD, wmma::mem_row_major);
        __syncthreads();

        // ---- Epilogue: gates, c/h update; publish LL packets straight from regs ----
        float hv[2];
        #pragma unroll
        for (int j = 0; j < 2; ++j) {
            int b = b0 + j*8;
            const float* zr = &sZ[b*ZPAD];
            float zg = zr[uu]          + sBias[uu];
            float zi = zr[UPC   + uu]  + sBias[UPC   + uu];
            float zf = zr[2*UPC + uu]  + sBias[2*UPC + uu];
            float zo = zr[3*UPC + uu]  + sBias[3*UPC + uu];
            float gv = tanh_fast(zg);
            float iv = sigm_fast(zi);
            float fv = sigm_fast(zf);
            float ov = sigm_fast(zo);
            float& c = j ? c1 : c0;
            c = gv*iv + c*fv;
            hv[j] = tanh_fast(c) * ov;
            sH[b*UPC + uu] = __float2half_rn(hv[j]);
            if (t == TSEQ-1) g_h32[(bg*MB + b)*HID + ug*UPC + uu] = hv[j];
        }

        // pack + send: even lanes emit packets for (row b0, units uu..uu+1) and (row b0+8, ...)
        if (t < TSEQ-1) {
            unsigned my = ((unsigned)__half_as_ushort(__float2half_rn(hv[0])))
                        | (((unsigned)__half_as_ushort(__float2half_rn(hv[1]))) << 16);
            unsigned other = __shfl_xor_sync(0xffffffffu, my, 1);
            if (!(lid & 1)) {
                unsigned pa = (my & 0xFFFFu)  | ((other & 0xFFFFu) << 16);       // row b0
                unsigned pb = (my >> 16)      | (other & 0xFFFF0000u);           // row b0+8
                unsigned long long tag = ((unsigned long long)(unsigned)(t + 1)) << 32;
                int up = lid >> 1;
                unsigned long long* dst = &g_hx[p ^ 1][bg][ug][0];
                ll_send(dst + (b0*16 + up),       tag | (unsigned long long)pa);
                ll_send(dst + ((b0+8)*16 + up),   tag | (unsigned long long)pb);
            }
        }
        __syncthreads();

        // ---- Phase X for step t+1: fc = x_{t+1} @ Wx^T (buffer p^1) — overlaps comm ----
        wmma::fill_fragment(fc, 0.0f);
        const __half* sAx = sA + (p^1)*SA_ELEMS;
        #pragma unroll
        for (int kk = KH; kk < KSTEPS; ++kk) {
            wmma::load_matrix_sync(fa, sAx + kk*16, KPAD);
            wmma::mma_sync(fc, fa, fbr[kk], fc);
        }

        // ---- stage x_{t+2} into buffer p x-region ----
        {
            int row = tid >> 4;
            int qq  = (tid & 15) * 8;
            __half2 h0 = __floats2half2_rn(xv0.x, xv0.y), h1 = __floats2half2_rn(xv0.z, xv0.w);
            __half2 h2 = __floats2half2_rn(xv1.x, xv1.y), h3 = __floats2half2_rn(xv1.z, xv1.w);
            uint4 pk; pk.x = *(uint32_t*)&h0; pk.y = *(uint32_t*)&h1;
            pk.z = *(uint32_t*)&h2; pk.w = *(uint32_t*)&h3;
            *(uint4*)&sA[p*SA_ELEMS + row*KPAD + HID + qq] = pk;
        }
    }

    // ---- completion: publish g_h32 visibility, then ug==0 CTAs project ----
    __threadfence();
    __syncthreads();
    if (tid == 0) atomicAdd(&g_done[bg], 1u);

    if (ug == 0) {
        if (tid == 0) {
            while (ld_acquire_gpu(&g_done[bg]) < NUG) { }
        }
        __syncthreads();

        const int b     = tid >> 4;
        const int obase = (tid & 15) * 8;
        float acc[8];
        #pragma unroll
        for (int rr = 0; rr < 8; ++rr) acc[rr] = bp[obase + rr];
        const float* hrow = &g_h32[(bg*MB + b)*HID];
        for (int k = 0; k < HID; k += 4) {
            float4 hvv = __ldcg((const float4*)&hrow[k]);
            #pragma unroll
            for (int rr = 0; rr < 8; ++rr) {
                acc[rr] = fmaf(hvv.x, Wp[(obase + rr)*HID + k],     acc[rr]);
                acc[rr] = fmaf(hvv.y, Wp[(obase + rr)*HID + k + 1], acc[rr]);
                acc[rr] = fmaf(hvv.z, Wp[(obase + rr)*HID + k + 2], acc[rr]);
                acc[rr] = fmaf(hvv.w, Wp[(obase + rr)*HID + k + 3], acc[rr]);
            }
        }
        #pragma unroll
        for (int rr = 0; rr < 8; ++rr)
            out[(bg*MB + b)*OUT_D + obase + rr] = acc[rr];
    }
}

extern "C" void kernel_launch(void* const* d_in, const int* in_sizes, int n_in,
                              void* d_out, int out_size) {
    const float* x   = (const float*)d_in[0];
    const float* Wgx = (const float*)d_in[1];
    const float* bgx = (const float*)d_in[2];
    const float* Wgh = (const float*)d_in[3];
    const float* Wix = (const float*)d_in[4];
    const float* bix = (const float*)d_in[5];
    const float* Wih = (const float*)d_in[6];
    const float* Wfx = (const float*)d_in[7];
    const float* bfx = (const float*)d_in[8];
    const float* Wfh = (const float*)d_in[9];
    const float* Wox = (const float*)d_in[10];
    const float* box = (const float*)d_in[11];
    const float* Woh = (const float*)d_in[12];
    const float* Wp  = (const float*)d_in[13];
    const float* bp  = (const float*)d_in[14];
    float* out = (float*)d_out;

    static bool attr_set = false;
    if (!attr_set) {
        cudaFuncSetAttribute(lstm_ll_kernel,
                             cudaFuncAttributeMaxDynamicSharedMemorySize, SMEM_BYTES);
        attr_set = true;
    }

    lstm_init_kernel<<<32, 256>>>();
    lstm_ll_kernel<<<NBG*NUG, NTH, SMEM_BYTES>>>(
        x, Wgx, bgx, Wgh, Wix, bix, Wih, Wfx, bfx, Wfh, Wox, box, Woh, Wp, bp, out);
}